// round 14
// baseline (speedup 1.0000x reference)
#include <cuda_runtime.h>
#include <cuda_fp16.h>
#include <stdint.h>
#include <math.h>

#define NN 100000
#define F0 128
#define F1 64
#define F2 128
#define F3 256
#define MAXF 256
#define MAXE 1600000
#define SCAN_BLK 1024
#define NBLK ((NN + SCAN_BLK - 1) / SCAN_BLK)

// deg fixed-point: bits [0:44) = deg * 2^20 ; bits [44:64) = edge count
#define DEG_SHIFT 20
#define CNT_SHIFT 44
#define DEG_MASK ((1ULL << CNT_SHIFT) - 1ULL)

// ---------------- scratch (static device globals; no allocation) ----------------
__device__ unsigned long long g_pk[NN];     // packed {count, deg_fixed}
__device__ float  g_dinv[NN];
__device__ float  g_dinv2[NN];
__device__ int    g_part[NN];
__device__ int    g_bsum[NBLK];
__device__ int    g_rowptr[NN + 1];
__device__ int    g_cursor[NN];
__device__ int2   g_epack[MAXE];            // {src, float_bits(norm)} dst-sorted
__device__ int    g_is32;
__device__ __half g_hh[(size_t)NN * MAXF];  // half feature buffer A
__device__ __half g_xh[(size_t)NN * MAXF];  // half feature buffer B
__device__ float  g_gmax[F3];

// ---------------- init + dtype detect (fused) ----------------
__global__ void k_init_detect(unsigned long long* pk, int n, int* flag, float* gmax,
                              const long long* __restrict__ ei64, int ndet) {
    int i = blockIdx.x * blockDim.x + threadIdx.x;
    if (i == 0) *flag = 0;
    if (i < n) pk[i] = (1ULL << DEG_SHIFT);  // deg starts at self-loop weight 1.0
    if (i < F3) gmax[i] = 0.0f;
    if (i < ndet) {
        long long v = ei64[i];
        if (v < 0 || v >= (long long)n) atomicOr(flag, 1);
    }
}

// one 64-bit atomic per edge: count++ and deg += ew (fixed point)
__global__ void k_hist(const void* __restrict__ ei, int e,
                       const int* __restrict__ flag, const float* __restrict__ ew,
                       unsigned long long* __restrict__ pk) {
    int i = blockIdx.x * blockDim.x + threadIdx.x;
    if (i >= e) return;
    int d;
    if (*flag) d = ((const int*)ei)[e + i];
    else       d = (int)((const long long*)ei)[e + i];
    unsigned long long degq =
        (unsigned long long)(ew[i] * (float)(1 << DEG_SHIFT) + 0.5f);
    atomicAdd(&pk[d], (1ULL << CNT_SHIFT) | degq);
}

// ---------------- scan stage 1 ----------------
__global__ __launch_bounds__(256) void k_scan1(const unsigned long long* __restrict__ pk,
                                               int* __restrict__ out,
                                               int* __restrict__ bsum, int n) {
    __shared__ int ts[256];
    int t = threadIdx.x;
    int base = blockIdx.x * SCAN_BLK + t * 4;
    int v0 = 0, v1 = 0, v2 = 0, v3 = 0;
    if (base + 0 < n) v0 = (int)(pk[base + 0] >> CNT_SHIFT);
    if (base + 1 < n) v1 = (int)(pk[base + 1] >> CNT_SHIFT);
    if (base + 2 < n) v2 = (int)(pk[base + 2] >> CNT_SHIFT);
    if (base + 3 < n) v3 = (int)(pk[base + 3] >> CNT_SHIFT);
    int tsum = v0 + v1 + v2 + v3;
    ts[t] = tsum;
    __syncthreads();
    for (int off = 1; off < 256; off <<= 1) {
        int x = (t >= off) ? ts[t - off] : 0;
        __syncthreads();
        ts[t] += x;
        __syncthreads();
    }
    int excl = ts[t] - tsum;
    if (t == 255) bsum[blockIdx.x] = ts[255];
    if (base + 0 < n) out[base + 0] = excl;
    if (base + 1 < n) out[base + 1] = excl + v0;
    if (base + 2 < n) out[base + 2] = excl + v0 + v1;
    if (base + 3 < n) out[base + 3] = excl + v0 + v1 + v2;
}

// ---------------- scan stage 2+3 fused + dinv from packed deg ----------------
__global__ __launch_bounds__(256) void k_scan3f(
    int* __restrict__ rowptr, int* __restrict__ cursor,
    const int* __restrict__ part, const int* __restrict__ bsum, int nb,
    const unsigned long long* __restrict__ pk,
    float* __restrict__ dinv, float* __restrict__ dinv2,
    int n, int e) {
    __shared__ int s[128];
    __shared__ int ex[128];
    int t = threadIdx.x;
    int v = 0;
    if (t < 128) {
        v = (t < nb) ? bsum[t] : 0;
        s[t] = v;
    }
    __syncthreads();
    for (int off = 1; off < 128; off <<= 1) {
        int x = 0;
        if (t < 128 && t >= off) x = s[t - off];
        __syncthreads();
        if (t < 128) s[t] += x;
        __syncthreads();
    }
    if (t < 128) ex[t] = s[t] - v;
    __syncthreads();

    int i = blockIdx.x * blockDim.x + t;
    if (i < n) {
        int r = part[i] + ex[i / SCAN_BLK];
        rowptr[i] = r;
        cursor[i] = r;
        float d = (float)(pk[i] & DEG_MASK) * (1.0f / (float)(1 << DEG_SHIFT));
        dinv[i] = rsqrtf(d);
        dinv2[i] = 1.0f / d;
    }
    if (i == 0) rowptr[n] = e;
}

__global__ void k_sort(const void* __restrict__ ei, int e,
                       const int* __restrict__ flag,
                       const float* __restrict__ ew, const float* __restrict__ dinv,
                       int* __restrict__ cursor, int2* __restrict__ epack) {
    int i = blockIdx.x * blockDim.x + threadIdx.x;
    if (i >= e) return;
    int s, d;
    if (*flag) {
        const int* p = (const int*)ei;
        s = p[i]; d = p[e + i];
    } else {
        const long long* p = (const long long*)ei;
        s = (int)p[i]; d = (int)p[e + i];
    }
    int pos = atomicAdd(&cursor[d], 1);
    epack[pos] = make_int2(s, __float_as_int(dinv[s] * ew[i] * dinv[d]));
}

// ---------------- tf32 tensor-core GEMM: 128x64 tile, BK=16, 8 warps ----------------
__device__ __forceinline__ uint32_t f2tf(float f) {
    uint32_t u;
    asm("cvt.rna.tf32.f32 %0, %1;" : "=r"(u) : "f"(f));
    return u;
}

__device__ __forceinline__ void load_a8(const float* Ap, bool aok, uint32_t* t8) {
    float4 a0 = make_float4(0.f, 0.f, 0.f, 0.f), a1 = a0;
    if (aok) { a0 = *(const float4*)Ap; a1 = *(const float4*)(Ap + 4); }
    t8[0] = f2tf(a0.x); t8[1] = f2tf(a0.y); t8[2] = f2tf(a0.z); t8[3] = f2tf(a0.w);
    t8[4] = f2tf(a1.x); t8[5] = f2tf(a1.y); t8[6] = f2tf(a1.z); t8[7] = f2tf(a1.w);
}

__device__ __forceinline__ void load_a8(const __half* Ap, bool aok, uint32_t* t8) {
    uint4 raw = make_uint4(0u, 0u, 0u, 0u);
    if (aok) raw = *(const uint4*)Ap;
    const __half2* h = (const __half2*)&raw;
#pragma unroll
    for (int j = 0; j < 4; j++) {
        float2 f = __half22float2(h[j]);
        t8[2 * j + 0] = f2tf(f.x);
        t8[2 * j + 1] = f2tf(f.y);
    }
}

template <int EPI, typename TA>
__global__ __launch_bounds__(256) void k_tfgemm(
    const TA* __restrict__ A, const float* __restrict__ B,
    const float* __restrict__ bias, __half* __restrict__ Out,
    float* __restrict__ gmax, int M, int K, int N) {
    __shared__ uint32_t As[2][128][20];
    __shared__ uint32_t Bs[2][16][72];

    int tid = threadIdx.x;
    int lane = tid & 31, wid = tid >> 5;
    int warpM = wid & 3, warpN = wid >> 2;
    int bm = blockIdx.y * 128, bn = blockIdx.x * 64;

    int lr = tid >> 1;
    int lc = (tid & 1) << 3;
    int brr = tid >> 4;
    int bcc = (tid & 15) << 2;

    const TA* Ap = A + (size_t)(bm + lr) * K + lc;
    bool aok = (bm + lr) < M;
    const float* Bp = B + (size_t)brr * N + bn + bcc;

    float d[2][4][4];
#pragma unroll
    for (int mt = 0; mt < 2; mt++)
#pragma unroll
        for (int nt = 0; nt < 4; nt++)
#pragma unroll
            for (int j = 0; j < 4; j++) d[mt][nt][j] = 0.0f;

    int T = K >> 4;
    uint32_t a8[8];
    float4 bx;

    load_a8(Ap, aok, a8);
    bx = *(const float4*)Bp;
#pragma unroll
    for (int j = 0; j < 8; j++) As[0][lr][lc + j] = a8[j];
    Bs[0][brr][bcc + 0] = f2tf(bx.x); Bs[0][brr][bcc + 1] = f2tf(bx.y);
    Bs[0][brr][bcc + 2] = f2tf(bx.z); Bs[0][brr][bcc + 3] = f2tf(bx.w);
    __syncthreads();

    for (int t = 0; t < T; t++) {
        int buf = t & 1;
        if (t + 1 < T) {
            load_a8(Ap + (t + 1) * 16, aok, a8);
            bx = *(const float4*)(Bp + (size_t)(t + 1) * 16 * N);
        }
#pragma unroll
        for (int kk = 0; kk < 2; kk++) {
            int k0 = kk * 8 + (lane & 3);
            uint32_t a[2][4], b[4][2];
#pragma unroll
            for (int mt = 0; mt < 2; mt++) {
                int r = warpM * 32 + mt * 16 + (lane >> 2);
                a[mt][0] = As[buf][r][k0];
                a[mt][1] = As[buf][r + 8][k0];
                a[mt][2] = As[buf][r][k0 + 4];
                a[mt][3] = As[buf][r + 8][k0 + 4];
            }
#pragma unroll
            for (int nt = 0; nt < 4; nt++) {
                int c = warpN * 32 + nt * 8 + (lane >> 2);
                b[nt][0] = Bs[buf][k0][c];
                b[nt][1] = Bs[buf][k0 + 4][c];
            }
#pragma unroll
            for (int mt = 0; mt < 2; mt++)
#pragma unroll
                for (int nt = 0; nt < 4; nt++) {
                    asm volatile(
                        "mma.sync.aligned.m16n8k8.row.col.f32.tf32.tf32.f32 "
                        "{%0,%1,%2,%3}, {%4,%5,%6,%7}, {%8,%9}, {%0,%1,%2,%3};"
                        : "+f"(d[mt][nt][0]), "+f"(d[mt][nt][1]),
                          "+f"(d[mt][nt][2]), "+f"(d[mt][nt][3])
                        : "r"(a[mt][0]), "r"(a[mt][1]), "r"(a[mt][2]), "r"(a[mt][3]),
                          "r"(b[nt][0]), "r"(b[nt][1]));
                }
        }
        if (t + 1 < T) {
            int nb2 = buf ^ 1;
#pragma unroll
            for (int j = 0; j < 8; j++) As[nb2][lr][lc + j] = a8[j];
            Bs[nb2][brr][bcc + 0] = f2tf(bx.x); Bs[nb2][brr][bcc + 1] = f2tf(bx.y);
            Bs[nb2][brr][bcc + 2] = f2tf(bx.z); Bs[nb2][brr][bcc + 3] = f2tf(bx.w);
        }
        __syncthreads();
    }

    if (EPI == 2) {
        __shared__ float sgm[64];
        if (tid < 64) sgm[tid] = 0.0f;
        __syncthreads();
#pragma unroll
        for (int mt = 0; mt < 2; mt++)
#pragma unroll
            for (int nt = 0; nt < 4; nt++) {
                int c = warpN * 32 + nt * 8 + 2 * (lane & 3);
                int r = bm + warpM * 32 + mt * 16 + (lane >> 2);
                float bv0 = bias[bn + c], bv1 = bias[bn + c + 1];
                float m0 = 0.0f, m1 = 0.0f;
                if (r < M) {
                    m0 = fmaxf(d[mt][nt][0] + bv0, 0.0f);
                    m1 = fmaxf(d[mt][nt][1] + bv1, 0.0f);
                }
                if (r + 8 < M) {
                    m0 = fmaxf(m0, fmaxf(d[mt][nt][2] + bv0, 0.0f));
                    m1 = fmaxf(m1, fmaxf(d[mt][nt][3] + bv1, 0.0f));
                }
                atomicMax((int*)&sgm[c], __float_as_int(m0));
                atomicMax((int*)&sgm[c + 1], __float_as_int(m1));
            }
        __syncthreads();
        if (tid < 64) atomicMax((int*)&gmax[bn + tid], __float_as_int(sgm[tid]));
    } else {
#pragma unroll
        for (int mt = 0; mt < 2; mt++)
#pragma unroll
            for (int nt = 0; nt < 4; nt++) {
                int c = warpN * 32 + nt * 8 + 2 * (lane & 3);
                int r = bm + warpM * 32 + mt * 16 + (lane >> 2);
                float bv0 = 0.0f, bv1 = 0.0f;
                if (EPI == 1) { bv0 = bias[bn + c]; bv1 = bias[bn + c + 1]; }
                if (r < M) {
                    float v0 = d[mt][nt][0], v1 = d[mt][nt][1];
                    if (EPI == 1) { v0 = fmaxf(v0 + bv0, 0.0f); v1 = fmaxf(v1 + bv1, 0.0f); }
                    *(__half2*)(Out + (size_t)r * N + bn + c) = __floats2half2_rn(v0, v1);
                }
                if (r + 8 < M) {
                    float v2 = d[mt][nt][2], v3 = d[mt][nt][3];
                    if (EPI == 1) { v2 = fmaxf(v2 + bv0, 0.0f); v3 = fmaxf(v3 + bv1, 0.0f); }
                    *(__half2*)(Out + (size_t)(r + 8) * N + bn + c) = __floats2half2_rn(v2, v3);
                }
            }
    }
}

// ---------------- software-pipelined CSR aggregation ----------------
// STRIDE = uint4 elements per feature row (8 for F=64, 16 for F=128)
// Pipeline: gathers for batch i overlap edge-record loads for batch i+1.
template <int STRIDE, int LANES, bool REL>
__device__ __forceinline__ void agg_body(
    const int* __restrict__ rowptr, const int2* __restrict__ ep,
    const __half* __restrict__ H, const float* __restrict__ dinv2,
    const float* __restrict__ bias, __half* __restrict__ out,
    int node, int li) {
    const uint4* Hv = (const uint4*)H;
    float a0, a1, a2, a3, a4, a5, a6, a7;
    {
        uint4 r = __ldcg(&Hv[(size_t)node * STRIDE + li]);
        float2 f0 = __half22float2(*(__half2*)&r.x);
        float2 f1 = __half22float2(*(__half2*)&r.y);
        float2 f2 = __half22float2(*(__half2*)&r.z);
        float2 f3 = __half22float2(*(__half2*)&r.w);
        float d2 = dinv2[node];
        a0 = f0.x * d2; a1 = f0.y * d2; a2 = f1.x * d2; a3 = f1.y * d2;
        a4 = f2.x * d2; a5 = f2.y * d2; a6 = f3.x * d2; a7 = f3.y * d2;
    }
    int e = rowptr[node], r1 = rowptr[node + 1];

    int2 c0, c1, c2, c3;
    bool have = (e + 3 < r1);
    if (have) {
        c0 = __ldcs(&ep[e]);     c1 = __ldcs(&ep[e + 1]);
        c2 = __ldcs(&ep[e + 2]); c3 = __ldcs(&ep[e + 3]);
    }
    while (have) {
        // stage 1: issue gathers for current batch
        uint4 r0 = __ldcg(&Hv[(size_t)c0.x * STRIDE + li]);
        uint4 r1v = __ldcg(&Hv[(size_t)c1.x * STRIDE + li]);
        uint4 r2 = __ldcg(&Hv[(size_t)c2.x * STRIDE + li]);
        uint4 r3 = __ldcg(&Hv[(size_t)c3.x * STRIDE + li]);
        // stage 2: prefetch next batch of edge records (independent of gathers)
        int en = e + 4;
        bool haveN = (en + 3 < r1);
        int2 n0, n1, n2, n3;
        if (haveN) {
            n0 = __ldcs(&ep[en]);     n1 = __ldcs(&ep[en + 1]);
            n2 = __ldcs(&ep[en + 2]); n3 = __ldcs(&ep[en + 3]);
        }
        // stage 3: consume gathers
        float m0 = __int_as_float(c0.y), m1 = __int_as_float(c1.y);
        float m2 = __int_as_float(c2.y), m3 = __int_as_float(c3.y);
        float2 p0 = __half22float2(*(__half2*)&r0.x), p1 = __half22float2(*(__half2*)&r0.y);
        float2 p2 = __half22float2(*(__half2*)&r0.z), p3 = __half22float2(*(__half2*)&r0.w);
        float2 q0 = __half22float2(*(__half2*)&r1v.x), q1 = __half22float2(*(__half2*)&r1v.y);
        float2 q2 = __half22float2(*(__half2*)&r1v.z), q3 = __half22float2(*(__half2*)&r1v.w);
        float2 s0 = __half22float2(*(__half2*)&r2.x), s1 = __half22float2(*(__half2*)&r2.y);
        float2 s2 = __half22float2(*(__half2*)&r2.z), s3 = __half22float2(*(__half2*)&r2.w);
        float2 t0 = __half22float2(*(__half2*)&r3.x), t1 = __half22float2(*(__half2*)&r3.y);
        float2 t2 = __half22float2(*(__half2*)&r3.z), t3 = __half22float2(*(__half2*)&r3.w);
        a0 += p0.x * m0 + q0.x * m1 + s0.x * m2 + t0.x * m3;
        a1 += p0.y * m0 + q0.y * m1 + s0.y * m2 + t0.y * m3;
        a2 += p1.x * m0 + q1.x * m1 + s1.x * m2 + t1.x * m3;
        a3 += p1.y * m0 + q1.y * m1 + s1.y * m2 + t1.y * m3;
        a4 += p2.x * m0 + q2.x * m1 + s2.x * m2 + t2.x * m3;
        a5 += p2.y * m0 + q2.y * m1 + s2.y * m2 + t2.y * m3;
        a6 += p3.x * m0 + q3.x * m1 + s3.x * m2 + t3.x * m3;
        a7 += p3.y * m0 + q3.y * m1 + s3.y * m2 + t3.y * m3;
        e = en;
        c0 = n0; c1 = n1; c2 = n2; c3 = n3;
        have = haveN;
    }
    for (; e < r1; e++) {
        int2 e0 = __ldcs(&ep[e]);
        float n0 = __int_as_float(e0.y);
        uint4 r0 = __ldcg(&Hv[(size_t)e0.x * STRIDE + li]);
        float2 p0 = __half22float2(*(__half2*)&r0.x), p1 = __half22float2(*(__half2*)&r0.y);
        float2 p2 = __half22float2(*(__half2*)&r0.z), p3 = __half22float2(*(__half2*)&r0.w);
        a0 += p0.x * n0; a1 += p0.y * n0; a2 += p1.x * n0; a3 += p1.y * n0;
        a4 += p2.x * n0; a5 += p2.y * n0; a6 += p3.x * n0; a7 += p3.y * n0;
    }
    if (REL) {
        float4 bv0 = ((const float4*)bias)[2 * li];
        float4 bv1 = ((const float4*)bias)[2 * li + 1];
        a0 = fmaxf(a0 + bv0.x, 0.0f); a1 = fmaxf(a1 + bv0.y, 0.0f);
        a2 = fmaxf(a2 + bv0.z, 0.0f); a3 = fmaxf(a3 + bv0.w, 0.0f);
        a4 = fmaxf(a4 + bv1.x, 0.0f); a5 = fmaxf(a5 + bv1.y, 0.0f);
        a6 = fmaxf(a6 + bv1.z, 0.0f); a7 = fmaxf(a7 + bv1.w, 0.0f);
    }
    uint4 o;
    *(__half2*)&o.x = __floats2half2_rn(a0, a1);
    *(__half2*)&o.y = __floats2half2_rn(a2, a3);
    *(__half2*)&o.z = __floats2half2_rn(a4, a5);
    *(__half2*)&o.w = __floats2half2_rn(a6, a7);
    ((uint4*)out)[(size_t)node * STRIDE + li] = o;
}

template <bool REL>
__global__ __launch_bounds__(256) void k_agg64(
    const int* __restrict__ rowptr, const int2* __restrict__ ep,
    const __half* __restrict__ H, const float* __restrict__ dinv2,
    const float* __restrict__ bias, __half* __restrict__ out, int n) {
    int node = (int)((blockIdx.x * blockDim.x + threadIdx.x) >> 3);
    int li = threadIdx.x & 7;
    if (node >= n) return;
    agg_body<8, 8, REL>(rowptr, ep, H, dinv2, bias, out, node, li);
}

__global__ __launch_bounds__(256) void k_agg128(
    const int* __restrict__ rowptr, const int2* __restrict__ ep,
    const __half* __restrict__ H, const float* __restrict__ dinv2,
    __half* __restrict__ out, int n) {
    int node = (int)((blockIdx.x * blockDim.x + threadIdx.x) >> 4);
    int li = threadIdx.x & 15;
    if (node >= n) return;
    agg_body<16, 16, false>(rowptr, ep, H, dinv2, nullptr, out, node, li);
}

// ---------------- MLP head + log_softmax ----------------
__global__ void k_head(const float* __restrict__ gmax,
                       const float* __restrict__ Wl1, const float* __restrict__ bl1,
                       const float* __restrict__ Wl2, const float* __restrict__ bl2,
                       float* __restrict__ out) {
    __shared__ float g[256];
    __shared__ float h1[128];
    __shared__ float logits[10];
    int t = threadIdx.x;
    g[t] = gmax[t];
    __syncthreads();
    if (t < 128) {
        float s = bl1[t];
        for (int k = 0; k < 256; k++) s += g[k] * Wl1[k * 128 + t];
        h1[t] = fmaxf(s, 0.0f);
    }
    __syncthreads();
    if (t < 10) {
        float s = bl2[t];
        for (int k = 0; k < 128; k++) s += h1[k] * Wl2[k * 10 + t];
        logits[t] = s;
    }
    __syncthreads();
    if (t == 0) {
        float m = -1e30f;
        for (int c = 0; c < 10; c++) m = fmaxf(m, logits[c]);
        float se = 0.0f;
        for (int c = 0; c < 10; c++) se += expf(logits[c] - m);
        float lse = logf(se);
        for (int c = 0; c < 10; c++) out[c] = logits[c] - m - lse;
    }
}

// ---------------- launch ----------------
extern "C" void kernel_launch(void* const* d_in, const int* in_sizes, int n_in,
                              void* d_out, int out_size) {
    const float* x   = (const float*)d_in[0];
    const void*  ei  = d_in[1];
    const float* ew  = (const float*)d_in[2];
    const float* W1  = (const float*)d_in[3];
    const float* b1  = (const float*)d_in[4];
    const float* W2  = (const float*)d_in[5];
    const float* b2  = (const float*)d_in[6];
    const float* W3  = (const float*)d_in[7];
    const float* b3  = (const float*)d_in[8];
    const float* Wl1 = (const float*)d_in[9];
    const float* bl1 = (const float*)d_in[10];
    const float* Wl2 = (const float*)d_in[11];
    const float* bl2 = (const float*)d_in[12];
    float* out = (float*)d_out;

    int E = in_sizes[2];
    int N = in_sizes[0] / F0;

    unsigned long long* pk;
    float *dinv, *dinv2, *gmax;
    int *part, *bsum, *rowptr, *cursor, *flag;
    int2* epack;
    __half *hh, *xh;
    cudaGetSymbolAddress((void**)&pk,     g_pk);
    cudaGetSymbolAddress((void**)&dinv,   g_dinv);
    cudaGetSymbolAddress((void**)&dinv2,  g_dinv2);
    cudaGetSymbolAddress((void**)&part,   g_part);
    cudaGetSymbolAddress((void**)&bsum,   g_bsum);
    cudaGetSymbolAddress((void**)&rowptr, g_rowptr);
    cudaGetSymbolAddress((void**)&cursor, g_cursor);
    cudaGetSymbolAddress((void**)&epack,  g_epack);
    cudaGetSymbolAddress((void**)&flag,   g_is32);
    cudaGetSymbolAddress((void**)&hh,     g_hh);
    cudaGetSymbolAddress((void**)&xh,     g_xh);
    cudaGetSymbolAddress((void**)&gmax,   g_gmax);

    int agg64Grid = (N + 31) / 32;
    int agg128Grid = (N + 15) / 16;
    int gy = (N + 127) / 128;
    int nb = (N + SCAN_BLK - 1) / SCAN_BLK;
    int det = E < 65536 ? E : 65536;

    cudaEvent_t evFork, evJoin;
    cudaEventCreateWithFlags(&evFork, cudaEventDisableTiming);
    cudaEventCreateWithFlags(&evJoin, cudaEventDisableTiming);

    // ---- fork: layer-1 GEMM (x W1) has no preprocessing dependencies ----
    cudaEventRecord(evFork, 0);
    cudaStreamWaitEvent(cudaStreamPerThread, evFork, 0);
    k_tfgemm<0, float><<<dim3(F1 / 64, gy), 256, 0, cudaStreamPerThread>>>(
        x, W1, nullptr, hh, nullptr, N, F0, F1);
    cudaEventRecord(evJoin, cudaStreamPerThread);

    // ---- preprocessing chain (default stream, concurrent with GEMM1) ----
    k_init_detect<<<(N + 255) / 256, 256>>>(pk, N, flag, gmax,
                                            (const long long*)ei, det);
    k_hist<<<(E + 255) / 256, 256>>>(ei, E, flag, ew, pk);
    k_scan1<<<nb, 256>>>(pk, part, bsum, N);
    k_scan3f<<<(N + 255) / 256, 256>>>(rowptr, cursor, part, bsum, nb,
                                       pk, dinv, dinv2, N, E);
    k_sort<<<(E + 255) / 256, 256>>>(ei, E, flag, ew, dinv, cursor, epack);

    // ---- join ----
    cudaStreamWaitEvent(0, evJoin, 0);

    // ---- layer 1 agg: xh = relu(A_hat hh + b1) ----
    k_agg64<true><<<agg64Grid, 256>>>(rowptr, epack, hh, dinv2, b1, xh, N);

    // ---- layer 2 ----
    k_agg64<false><<<agg64Grid, 256>>>(rowptr, epack, xh, dinv2, nullptr, hh, N);
    k_tfgemm<1, __half><<<dim3(F2 / 64, gy), 256>>>(hh, W2, b2, xh, nullptr, N, F1, F2);

    // ---- layer 3 ----
    k_agg128<<<agg128Grid, 256>>>(rowptr, epack, xh, dinv2, hh, N);
    k_tfgemm<2, __half><<<dim3(F3 / 64, gy), 256>>>(hh, W3, b3, nullptr, gmax, N, F2, F3);

    k_head<<<1, 256>>>(gmax, Wl1, bl1, Wl2, bl2, out);

    cudaEventDestroy(evFork);
    cudaEventDestroy(evJoin);
}

// round 15
// speedup vs baseline: 1.0265x; 1.0265x over previous
#include <cuda_runtime.h>
#include <cuda_fp16.h>
#include <stdint.h>
#include <math.h>

#define NN 100000
#define F0 128
#define F1 64
#define F2 128
#define F3 256
#define MAXF 256
#define MAXE 1600000
#define SCAN_BLK 1024
#define NBLK ((NN + SCAN_BLK - 1) / SCAN_BLK)

// deg fixed-point: bits [0:44) = deg * 2^20 ; bits [44:64) = edge count
#define DEG_SHIFT 20
#define CNT_SHIFT 44
#define DEG_MASK ((1ULL << CNT_SHIFT) - 1ULL)

// ---------------- scratch (static device globals; no allocation) ----------------
__device__ unsigned long long g_pk[NN];     // packed {count, deg_fixed}
__device__ float  g_dinv[NN];
__device__ float  g_dinv2[NN];
__device__ int    g_part[NN];
__device__ int    g_bsum[NBLK];
__device__ int    g_rowptr[NN + 1];
__device__ int    g_cursor[NN];
__device__ int2   g_epack[MAXE];            // {src, float_bits(norm)} dst-sorted
__device__ int    g_is32;
__device__ __half g_hh[(size_t)NN * MAXF];  // half feature buffer A
__device__ __half g_xh[(size_t)NN * MAXF];  // half feature buffer B
__device__ float  g_gmax[F3];

// ---------------- init + dtype detect (fused) ----------------
__global__ void k_init_detect(unsigned long long* pk, int n, int* flag, float* gmax,
                              const long long* __restrict__ ei64, int ndet) {
    int i = blockIdx.x * blockDim.x + threadIdx.x;
    if (i == 0) *flag = 0;
    if (i < n) pk[i] = (1ULL << DEG_SHIFT);  // deg starts at self-loop weight 1.0
    if (i < F3) gmax[i] = 0.0f;
    if (i < ndet) {
        long long v = ei64[i];
        if (v < 0 || v >= (long long)n) atomicOr(flag, 1);
    }
}

// one 64-bit atomic per edge: count++ and deg += ew (fixed point)
__global__ void k_hist(const void* __restrict__ ei, int e,
                       const int* __restrict__ flag, const float* __restrict__ ew,
                       unsigned long long* __restrict__ pk) {
    int i = blockIdx.x * blockDim.x + threadIdx.x;
    if (i >= e) return;
    int d;
    if (*flag) d = ((const int*)ei)[e + i];
    else       d = (int)((const long long*)ei)[e + i];
    unsigned long long degq =
        (unsigned long long)(__ldcs(&ew[i]) * (float)(1 << DEG_SHIFT) + 0.5f);
    atomicAdd(&pk[d], (1ULL << CNT_SHIFT) | degq);
}

// ---------------- scan stage 1 ----------------
__global__ __launch_bounds__(256) void k_scan1(const unsigned long long* __restrict__ pk,
                                               int* __restrict__ out,
                                               int* __restrict__ bsum, int n) {
    __shared__ int ts[256];
    int t = threadIdx.x;
    int base = blockIdx.x * SCAN_BLK + t * 4;
    int v0 = 0, v1 = 0, v2 = 0, v3 = 0;
    if (base + 0 < n) v0 = (int)(pk[base + 0] >> CNT_SHIFT);
    if (base + 1 < n) v1 = (int)(pk[base + 1] >> CNT_SHIFT);
    if (base + 2 < n) v2 = (int)(pk[base + 2] >> CNT_SHIFT);
    if (base + 3 < n) v3 = (int)(pk[base + 3] >> CNT_SHIFT);
    int tsum = v0 + v1 + v2 + v3;
    ts[t] = tsum;
    __syncthreads();
    for (int off = 1; off < 256; off <<= 1) {
        int x = (t >= off) ? ts[t - off] : 0;
        __syncthreads();
        ts[t] += x;
        __syncthreads();
    }
    int excl = ts[t] - tsum;
    if (t == 255) bsum[blockIdx.x] = ts[255];
    if (base + 0 < n) out[base + 0] = excl;
    if (base + 1 < n) out[base + 1] = excl + v0;
    if (base + 2 < n) out[base + 2] = excl + v0 + v1;
    if (base + 3 < n) out[base + 3] = excl + v0 + v1 + v2;
}

// ---------------- scan stage 2+3 fused + dinv from packed deg ----------------
__global__ __launch_bounds__(256) void k_scan3f(
    int* __restrict__ rowptr, int* __restrict__ cursor,
    const int* __restrict__ part, const int* __restrict__ bsum, int nb,
    const unsigned long long* __restrict__ pk,
    float* __restrict__ dinv, float* __restrict__ dinv2,
    int n, int e) {
    __shared__ int s[128];
    __shared__ int ex[128];
    int t = threadIdx.x;
    int v = 0;
    if (t < 128) {
        v = (t < nb) ? bsum[t] : 0;
        s[t] = v;
    }
    __syncthreads();
    for (int off = 1; off < 128; off <<= 1) {
        int x = 0;
        if (t < 128 && t >= off) x = s[t - off];
        __syncthreads();
        if (t < 128) s[t] += x;
        __syncthreads();
    }
    if (t < 128) ex[t] = s[t] - v;
    __syncthreads();

    int i = blockIdx.x * blockDim.x + t;
    if (i < n) {
        int r = part[i] + ex[i / SCAN_BLK];
        rowptr[i] = r;
        cursor[i] = r;
        float d = (float)(pk[i] & DEG_MASK) * (1.0f / (float)(1 << DEG_SHIFT));
        dinv[i] = rsqrtf(d);
        dinv2[i] = 1.0f / d;
    }
    if (i == 0) rowptr[n] = e;
}

__global__ void k_sort(const void* __restrict__ ei, int e,
                       const int* __restrict__ flag,
                       const float* __restrict__ ew, const float* __restrict__ dinv,
                       int* __restrict__ cursor, int2* __restrict__ epack) {
    int i = blockIdx.x * blockDim.x + threadIdx.x;
    if (i >= e) return;
    int s, d;
    if (*flag) {
        const int* p = (const int*)ei;
        s = p[i]; d = p[e + i];
    } else {
        const long long* p = (const long long*)ei;
        s = (int)p[i]; d = (int)p[e + i];
    }
    int pos = atomicAdd(&cursor[d], 1);
    epack[pos] = make_int2(s, __float_as_int(dinv[s] * __ldcs(&ew[i]) * dinv[d]));
}

// ---------------- tf32 tensor-core GEMM: 128x64 tile, BK=16, 8 warps ----------------
__device__ __forceinline__ uint32_t f2tf(float f) {
    uint32_t u;
    asm("cvt.rna.tf32.f32 %0, %1;" : "=r"(u) : "f"(f));
    return u;
}

__device__ __forceinline__ void load_a8(const float* Ap, bool aok, uint32_t* t8) {
    float4 a0 = make_float4(0.f, 0.f, 0.f, 0.f), a1 = a0;
    if (aok) { a0 = *(const float4*)Ap; a1 = *(const float4*)(Ap + 4); }
    t8[0] = f2tf(a0.x); t8[1] = f2tf(a0.y); t8[2] = f2tf(a0.z); t8[3] = f2tf(a0.w);
    t8[4] = f2tf(a1.x); t8[5] = f2tf(a1.y); t8[6] = f2tf(a1.z); t8[7] = f2tf(a1.w);
}

__device__ __forceinline__ void load_a8(const __half* Ap, bool aok, uint32_t* t8) {
    uint4 raw = make_uint4(0u, 0u, 0u, 0u);
    if (aok) raw = *(const uint4*)Ap;
    const __half2* h = (const __half2*)&raw;
#pragma unroll
    for (int j = 0; j < 4; j++) {
        float2 f = __half22float2(h[j]);
        t8[2 * j + 0] = f2tf(f.x);
        t8[2 * j + 1] = f2tf(f.y);
    }
}

template <int EPI, typename TA>
__global__ __launch_bounds__(256) void k_tfgemm(
    const TA* __restrict__ A, const float* __restrict__ B,
    const float* __restrict__ bias, __half* __restrict__ Out,
    float* __restrict__ gmax, int M, int K, int N) {
    __shared__ uint32_t As[2][128][20];
    __shared__ uint32_t Bs[2][16][72];

    int tid = threadIdx.x;
    int lane = tid & 31, wid = tid >> 5;
    int warpM = wid & 3, warpN = wid >> 2;
    int bm = blockIdx.y * 128, bn = blockIdx.x * 64;

    int lr = tid >> 1;
    int lc = (tid & 1) << 3;
    int brr = tid >> 4;
    int bcc = (tid & 15) << 2;

    const TA* Ap = A + (size_t)(bm + lr) * K + lc;
    bool aok = (bm + lr) < M;
    const float* Bp = B + (size_t)brr * N + bn + bcc;

    float d[2][4][4];
#pragma unroll
    for (int mt = 0; mt < 2; mt++)
#pragma unroll
        for (int nt = 0; nt < 4; nt++)
#pragma unroll
            for (int j = 0; j < 4; j++) d[mt][nt][j] = 0.0f;

    int T = K >> 4;
    uint32_t a8[8];
    float4 bx;

    load_a8(Ap, aok, a8);
    bx = *(const float4*)Bp;
#pragma unroll
    for (int j = 0; j < 8; j++) As[0][lr][lc + j] = a8[j];
    Bs[0][brr][bcc + 0] = f2tf(bx.x); Bs[0][brr][bcc + 1] = f2tf(bx.y);
    Bs[0][brr][bcc + 2] = f2tf(bx.z); Bs[0][brr][bcc + 3] = f2tf(bx.w);
    __syncthreads();

    for (int t = 0; t < T; t++) {
        int buf = t & 1;
        if (t + 1 < T) {
            load_a8(Ap + (t + 1) * 16, aok, a8);
            bx = *(const float4*)(Bp + (size_t)(t + 1) * 16 * N);
        }
#pragma unroll
        for (int kk = 0; kk < 2; kk++) {
            int k0 = kk * 8 + (lane & 3);
            uint32_t a[2][4], b[4][2];
#pragma unroll
            for (int mt = 0; mt < 2; mt++) {
                int r = warpM * 32 + mt * 16 + (lane >> 2);
                a[mt][0] = As[buf][r][k0];
                a[mt][1] = As[buf][r + 8][k0];
                a[mt][2] = As[buf][r][k0 + 4];
                a[mt][3] = As[buf][r + 8][k0 + 4];
            }
#pragma unroll
            for (int nt = 0; nt < 4; nt++) {
                int c = warpN * 32 + nt * 8 + (lane >> 2);
                b[nt][0] = Bs[buf][k0][c];
                b[nt][1] = Bs[buf][k0 + 4][c];
            }
#pragma unroll
            for (int mt = 0; mt < 2; mt++)
#pragma unroll
                for (int nt = 0; nt < 4; nt++) {
                    asm volatile(
                        "mma.sync.aligned.m16n8k8.row.col.f32.tf32.tf32.f32 "
                        "{%0,%1,%2,%3}, {%4,%5,%6,%7}, {%8,%9}, {%0,%1,%2,%3};"
                        : "+f"(d[mt][nt][0]), "+f"(d[mt][nt][1]),
                          "+f"(d[mt][nt][2]), "+f"(d[mt][nt][3])
                        : "r"(a[mt][0]), "r"(a[mt][1]), "r"(a[mt][2]), "r"(a[mt][3]),
                          "r"(b[nt][0]), "r"(b[nt][1]));
                }
        }
        if (t + 1 < T) {
            int nb2 = buf ^ 1;
#pragma unroll
            for (int j = 0; j < 8; j++) As[nb2][lr][lc + j] = a8[j];
            Bs[nb2][brr][bcc + 0] = f2tf(bx.x); Bs[nb2][brr][bcc + 1] = f2tf(bx.y);
            Bs[nb2][brr][bcc + 2] = f2tf(bx.z); Bs[nb2][brr][bcc + 3] = f2tf(bx.w);
        }
        __syncthreads();
    }

    if (EPI == 2) {
        __shared__ float sgm[64];
        if (tid < 64) sgm[tid] = 0.0f;
        __syncthreads();
#pragma unroll
        for (int mt = 0; mt < 2; mt++)
#pragma unroll
            for (int nt = 0; nt < 4; nt++) {
                int c = warpN * 32 + nt * 8 + 2 * (lane & 3);
                int r = bm + warpM * 32 + mt * 16 + (lane >> 2);
                float bv0 = bias[bn + c], bv1 = bias[bn + c + 1];
                float m0 = 0.0f, m1 = 0.0f;
                if (r < M) {
                    m0 = fmaxf(d[mt][nt][0] + bv0, 0.0f);
                    m1 = fmaxf(d[mt][nt][1] + bv1, 0.0f);
                }
                if (r + 8 < M) {
                    m0 = fmaxf(m0, fmaxf(d[mt][nt][2] + bv0, 0.0f));
                    m1 = fmaxf(m1, fmaxf(d[mt][nt][3] + bv1, 0.0f));
                }
                atomicMax((int*)&sgm[c], __float_as_int(m0));
                atomicMax((int*)&sgm[c + 1], __float_as_int(m1));
            }
        __syncthreads();
        if (tid < 64) atomicMax((int*)&gmax[bn + tid], __float_as_int(sgm[tid]));
    } else {
#pragma unroll
        for (int mt = 0; mt < 2; mt++)
#pragma unroll
            for (int nt = 0; nt < 4; nt++) {
                int c = warpN * 32 + nt * 8 + 2 * (lane & 3);
                int r = bm + warpM * 32 + mt * 16 + (lane >> 2);
                float bv0 = 0.0f, bv1 = 0.0f;
                if (EPI == 1) { bv0 = bias[bn + c]; bv1 = bias[bn + c + 1]; }
                if (r < M) {
                    float v0 = d[mt][nt][0], v1 = d[mt][nt][1];
                    if (EPI == 1) { v0 = fmaxf(v0 + bv0, 0.0f); v1 = fmaxf(v1 + bv1, 0.0f); }
                    *(__half2*)(Out + (size_t)r * N + bn + c) = __floats2half2_rn(v0, v1);
                }
                if (r + 8 < M) {
                    float v2 = d[mt][nt][2], v3 = d[mt][nt][3];
                    if (EPI == 1) { v2 = fmaxf(v2 + bv0, 0.0f); v3 = fmaxf(v3 + bv1, 0.0f); }
                    *(__half2*)(Out + (size_t)(r + 8) * N + bn + c) = __floats2half2_rn(v2, v3);
                }
            }
    }
}

// ---------------- CSR aggregation, F=64: QUARTER-WARP per node (R13 form) ----------------
template <bool REL>
__global__ __launch_bounds__(256) void k_agg64(
    const int* __restrict__ rowptr, const int2* __restrict__ ep,
    const __half* __restrict__ H, const float* __restrict__ dinv2,
    const float* __restrict__ bias, __half* __restrict__ out, int n) {
    int qw = (int)((blockIdx.x * blockDim.x + threadIdx.x) >> 3);
    int li = threadIdx.x & 7;
    if (qw >= n) return;

    const uint4* Hv = (const uint4*)H;
    float a0, a1, a2, a3, a4, a5, a6, a7;
    {
        uint4 r = __ldcg(&Hv[(size_t)qw * 8 + li]);
        float2 f0 = __half22float2(*(__half2*)&r.x);
        float2 f1 = __half22float2(*(__half2*)&r.y);
        float2 f2 = __half22float2(*(__half2*)&r.z);
        float2 f3 = __half22float2(*(__half2*)&r.w);
        float d2 = dinv2[qw];
        a0 = f0.x * d2; a1 = f0.y * d2; a2 = f1.x * d2; a3 = f1.y * d2;
        a4 = f2.x * d2; a5 = f2.y * d2; a6 = f3.x * d2; a7 = f3.y * d2;
    }
    int e = rowptr[qw], r1 = rowptr[qw + 1];
    for (; e + 3 < r1; e += 4) {
        int2 e0 = __ldcs(&ep[e]), e1 = __ldcs(&ep[e + 1]);
        int2 e2 = __ldcs(&ep[e + 2]), e3 = __ldcs(&ep[e + 3]);
        float n0 = __int_as_float(e0.y), n1 = __int_as_float(e1.y);
        float n2 = __int_as_float(e2.y), n3 = __int_as_float(e3.y);
        uint4 r0 = __ldcg(&Hv[(size_t)e0.x * 8 + li]);
        uint4 r1v = __ldcg(&Hv[(size_t)e1.x * 8 + li]);
        uint4 r2 = __ldcg(&Hv[(size_t)e2.x * 8 + li]);
        uint4 r3 = __ldcg(&Hv[(size_t)e3.x * 8 + li]);
        float2 p0 = __half22float2(*(__half2*)&r0.x), p1 = __half22float2(*(__half2*)&r0.y);
        float2 p2 = __half22float2(*(__half2*)&r0.z), p3 = __half22float2(*(__half2*)&r0.w);
        float2 q0 = __half22float2(*(__half2*)&r1v.x), q1 = __half22float2(*(__half2*)&r1v.y);
        float2 q2 = __half22float2(*(__half2*)&r1v.z), q3 = __half22float2(*(__half2*)&r1v.w);
        float2 s0 = __half22float2(*(__half2*)&r2.x), s1 = __half22float2(*(__half2*)&r2.y);
        float2 s2 = __half22float2(*(__half2*)&r2.z), s3 = __half22float2(*(__half2*)&r2.w);
        float2 t0 = __half22float2(*(__half2*)&r3.x), t1 = __half22float2(*(__half2*)&r3.y);
        float2 t2 = __half22float2(*(__half2*)&r3.z), t3 = __half22float2(*(__half2*)&r3.w);
        a0 += p0.x * n0 + q0.x * n1 + s0.x * n2 + t0.x * n3;
        a1 += p0.y * n0 + q0.y * n1 + s0.y * n2 + t0.y * n3;
        a2 += p1.x * n0 + q1.x * n1 + s1.x * n2 + t1.x * n3;
        a3 += p1.y * n0 + q1.y * n1 + s1.y * n2 + t1.y * n3;
        a4 += p2.x * n0 + q2.x * n1 + s2.x * n2 + t2.x * n3;
        a5 += p2.y * n0 + q2.y * n1 + s2.y * n2 + t2.y * n3;
        a6 += p3.x * n0 + q3.x * n1 + s3.x * n2 + t3.x * n3;
        a7 += p3.y * n0 + q3.y * n1 + s3.y * n2 + t3.y * n3;
    }
    for (; e < r1; e++) {
        int2 e0 = __ldcs(&ep[e]);
        float n0 = __int_as_float(e0.y);
        uint4 r0 = __ldcg(&Hv[(size_t)e0.x * 8 + li]);
        float2 p0 = __half22float2(*(__half2*)&r0.x), p1 = __half22float2(*(__half2*)&r0.y);
        float2 p2 = __half22float2(*(__half2*)&r0.z), p3 = __half22float2(*(__half2*)&r0.w);
        a0 += p0.x * n0; a1 += p0.y * n0; a2 += p1.x * n0; a3 += p1.y * n0;
        a4 += p2.x * n0; a5 += p2.y * n0; a6 += p3.x * n0; a7 += p3.y * n0;
    }
    if (REL) {
        float4 bv0 = ((const float4*)bias)[2 * li];
        float4 bv1 = ((const float4*)bias)[2 * li + 1];
        a0 = fmaxf(a0 + bv0.x, 0.0f); a1 = fmaxf(a1 + bv0.y, 0.0f);
        a2 = fmaxf(a2 + bv0.z, 0.0f); a3 = fmaxf(a3 + bv0.w, 0.0f);
        a4 = fmaxf(a4 + bv1.x, 0.0f); a5 = fmaxf(a5 + bv1.y, 0.0f);
        a6 = fmaxf(a6 + bv1.z, 0.0f); a7 = fmaxf(a7 + bv1.w, 0.0f);
    }
    uint4 o;
    *(__half2*)&o.x = __floats2half2_rn(a0, a1);
    *(__half2*)&o.y = __floats2half2_rn(a2, a3);
    *(__half2*)&o.z = __floats2half2_rn(a4, a5);
    *(__half2*)&o.w = __floats2half2_rn(a6, a7);
    ((uint4*)out)[(size_t)qw * 8 + li] = o;
}

// ---------------- CSR aggregation, F=128: HALF-WARP per node (R13 form) ----------------
__global__ __launch_bounds__(256) void k_agg128(
    const int* __restrict__ rowptr, const int2* __restrict__ ep,
    const __half* __restrict__ H, const float* __restrict__ dinv2,
    __half* __restrict__ out, int n) {
    int hw = (int)((blockIdx.x * blockDim.x + threadIdx.x) >> 4);
    int li = threadIdx.x & 15;
    if (hw >= n) return;

    const uint4* Hv = (const uint4*)H;
    float a0, a1, a2, a3, a4, a5, a6, a7;
    {
        uint4 r = __ldcg(&Hv[(size_t)hw * 16 + li]);
        float2 f0 = __half22float2(*(__half2*)&r.x);
        float2 f1 = __half22float2(*(__half2*)&r.y);
        float2 f2 = __half22float2(*(__half2*)&r.z);
        float2 f3 = __half22float2(*(__half2*)&r.w);
        float d2 = dinv2[hw];
        a0 = f0.x * d2; a1 = f0.y * d2; a2 = f1.x * d2; a3 = f1.y * d2;
        a4 = f2.x * d2; a5 = f2.y * d2; a6 = f3.x * d2; a7 = f3.y * d2;
    }
    int e = rowptr[hw], r1 = rowptr[hw + 1];
    for (; e + 3 < r1; e += 4) {
        int2 e0 = __ldcs(&ep[e]), e1 = __ldcs(&ep[e + 1]);
        int2 e2 = __ldcs(&ep[e + 2]), e3 = __ldcs(&ep[e + 3]);
        float n0 = __int_as_float(e0.y), n1 = __int_as_float(e1.y);
        float n2 = __int_as_float(e2.y), n3 = __int_as_float(e3.y);
        uint4 r0 = __ldcg(&Hv[(size_t)e0.x * 16 + li]);
        uint4 r1v = __ldcg(&Hv[(size_t)e1.x * 16 + li]);
        uint4 r2 = __ldcg(&Hv[(size_t)e2.x * 16 + li]);
        uint4 r3 = __ldcg(&Hv[(size_t)e3.x * 16 + li]);
        float2 p0 = __half22float2(*(__half2*)&r0.x), p1 = __half22float2(*(__half2*)&r0.y);
        float2 p2 = __half22float2(*(__half2*)&r0.z), p3 = __half22float2(*(__half2*)&r0.w);
        float2 q0 = __half22float2(*(__half2*)&r1v.x), q1 = __half22float2(*(__half2*)&r1v.y);
        float2 q2 = __half22float2(*(__half2*)&r1v.z), q3 = __half22float2(*(__half2*)&r1v.w);
        float2 s0 = __half22float2(*(__half2*)&r2.x), s1 = __half22float2(*(__half2*)&r2.y);
        float2 s2 = __half22float2(*(__half2*)&r2.z), s3 = __half22float2(*(__half2*)&r2.w);
        float2 t0 = __half22float2(*(__half2*)&r3.x), t1 = __half22float2(*(__half2*)&r3.y);
        float2 t2 = __half22float2(*(__half2*)&r3.z), t3 = __half22float2(*(__half2*)&r3.w);
        a0 += p0.x * n0 + q0.x * n1 + s0.x * n2 + t0.x * n3;
        a1 += p0.y * n0 + q0.y * n1 + s0.y * n2 + t0.y * n3;
        a2 += p1.x * n0 + q1.x * n1 + s1.x * n2 + t1.x * n3;
        a3 += p1.y * n0 + q1.y * n1 + s1.y * n2 + t1.y * n3;
        a4 += p2.x * n0 + q2.x * n1 + s2.x * n2 + t2.x * n3;
        a5 += p2.y * n0 + q2.y * n1 + s2.y * n2 + t2.y * n3;
        a6 += p3.x * n0 + q3.x * n1 + s3.x * n2 + t3.x * n3;
        a7 += p3.y * n0 + q3.y * n1 + s3.y * n2 + t3.y * n3;
    }
    for (; e < r1; e++) {
        int2 e0 = __ldcs(&ep[e]);
        float n0 = __int_as_float(e0.y);
        uint4 r0 = __ldcg(&Hv[(size_t)e0.x * 16 + li]);
        float2 p0 = __half22float2(*(__half2*)&r0.x), p1 = __half22float2(*(__half2*)&r0.y);
        float2 p2 = __half22float2(*(__half2*)&r0.z), p3 = __half22float2(*(__half2*)&r0.w);
        a0 += p0.x * n0; a1 += p0.y * n0; a2 += p1.x * n0; a3 += p1.y * n0;
        a4 += p2.x * n0; a5 += p2.y * n0; a6 += p3.x * n0; a7 += p3.y * n0;
    }
    uint4 o;
    *(__half2*)&o.x = __floats2half2_rn(a0, a1);
    *(__half2*)&o.y = __floats2half2_rn(a2, a3);
    *(__half2*)&o.z = __floats2half2_rn(a4, a5);
    *(__half2*)&o.w = __floats2half2_rn(a6, a7);
    ((uint4*)out)[(size_t)hw * 16 + li] = o;
}

// ---------------- MLP head + log_softmax ----------------
__global__ void k_head(const float* __restrict__ gmax,
                       const float* __restrict__ Wl1, const float* __restrict__ bl1,
                       const float* __restrict__ Wl2, const float* __restrict__ bl2,
                       float* __restrict__ out) {
    __shared__ float g[256];
    __shared__ float h1[128];
    __shared__ float logits[10];
    int t = threadIdx.x;
    g[t] = gmax[t];
    __syncthreads();
    if (t < 128) {
        float s = bl1[t];
        for (int k = 0; k < 256; k++) s += g[k] * Wl1[k * 128 + t];
        h1[t] = fmaxf(s, 0.0f);
    }
    __syncthreads();
    if (t < 10) {
        float s = bl2[t];
        for (int k = 0; k < 128; k++) s += h1[k] * Wl2[k * 10 + t];
        logits[t] = s;
    }
    __syncthreads();
    if (t == 0) {
        float m = -1e30f;
        for (int c = 0; c < 10; c++) m = fmaxf(m, logits[c]);
        float se = 0.0f;
        for (int c = 0; c < 10; c++) se += expf(logits[c] - m);
        float lse = logf(se);
        for (int c = 0; c < 10; c++) out[c] = logits[c] - m - lse;
    }
}

// ---------------- launch ----------------
extern "C" void kernel_launch(void* const* d_in, const int* in_sizes, int n_in,
                              void* d_out, int out_size) {
    const float* x   = (const float*)d_in[0];
    const void*  ei  = d_in[1];
    const float* ew  = (const float*)d_in[2];
    const float* W1  = (const float*)d_in[3];
    const float* b1  = (const float*)d_in[4];
    const float* W2  = (const float*)d_in[5];
    const float* b2  = (const float*)d_in[6];
    const float* W3  = (const float*)d_in[7];
    const float* b3  = (const float*)d_in[8];
    const float* Wl1 = (const float*)d_in[9];
    const float* bl1 = (const float*)d_in[10];
    const float* Wl2 = (const float*)d_in[11];
    const float* bl2 = (const float*)d_in[12];
    float* out = (float*)d_out;

    int E = in_sizes[2];
    int N = in_sizes[0] / F0;

    unsigned long long* pk;
    float *dinv, *dinv2, *gmax;
    int *part, *bsum, *rowptr, *cursor, *flag;
    int2* epack;
    __half *hh, *xh;
    cudaGetSymbolAddress((void**)&pk,     g_pk);
    cudaGetSymbolAddress((void**)&dinv,   g_dinv);
    cudaGetSymbolAddress((void**)&dinv2,  g_dinv2);
    cudaGetSymbolAddress((void**)&part,   g_part);
    cudaGetSymbolAddress((void**)&bsum,   g_bsum);
    cudaGetSymbolAddress((void**)&rowptr, g_rowptr);
    cudaGetSymbolAddress((void**)&cursor, g_cursor);
    cudaGetSymbolAddress((void**)&epack,  g_epack);
    cudaGetSymbolAddress((void**)&flag,   g_is32);
    cudaGetSymbolAddress((void**)&hh,     g_hh);
    cudaGetSymbolAddress((void**)&xh,     g_xh);
    cudaGetSymbolAddress((void**)&gmax,   g_gmax);

    int agg64Grid = (N + 31) / 32;
    int agg128Grid = (N + 15) / 16;
    int gy = (N + 127) / 128;
    int nb = (N + SCAN_BLK - 1) / SCAN_BLK;
    int det = E < 65536 ? E : 65536;

    cudaEvent_t evFork, evJoin;
    cudaEventCreateWithFlags(&evFork, cudaEventDisableTiming);
    cudaEventCreateWithFlags(&evJoin, cudaEventDisableTiming);

    // ---- fork: layer-1 GEMM (x W1) has no preprocessing dependencies ----
    cudaEventRecord(evFork, 0);
    cudaStreamWaitEvent(cudaStreamPerThread, evFork, 0);
    k_tfgemm<0, float><<<dim3(F1 / 64, gy), 256, 0, cudaStreamPerThread>>>(
        x, W1, nullptr, hh, nullptr, N, F0, F1);
    cudaEventRecord(evJoin, cudaStreamPerThread);

    // ---- preprocessing chain (default stream, concurrent with GEMM1) ----
    k_init_detect<<<(N + 255) / 256, 256>>>(pk, N, flag, gmax,
                                            (const long long*)ei, det);
    k_hist<<<(E + 255) / 256, 256>>>(ei, E, flag, ew, pk);
    k_scan1<<<nb, 256>>>(pk, part, bsum, N);
    k_scan3f<<<(N + 255) / 256, 256>>>(rowptr, cursor, part, bsum, nb,
                                       pk, dinv, dinv2, N, E);
    k_sort<<<(E + 255) / 256, 256>>>(ei, E, flag, ew, dinv, cursor, epack);

    // ---- join ----
    cudaStreamWaitEvent(0, evJoin, 0);

    // ---- layer 1 agg: xh = relu(A_hat hh + b1) ----
    k_agg64<true><<<agg64Grid, 256>>>(rowptr, epack, hh, dinv2, b1, xh, N);

    // ---- layer 2 ----
    k_agg64<false><<<agg64Grid, 256>>>(rowptr, epack, xh, dinv2, nullptr, hh, N);
    k_tfgemm<1, __half><<<dim3(F2 / 64, gy), 256>>>(hh, W2, b2, xh, nullptr, N, F1, F2);

    // ---- layer 3 ----
    k_agg128<<<agg128Grid, 256>>>(rowptr, epack, xh, dinv2, hh, N);
    k_tfgemm<2, __half><<<dim3(F3 / 64, gy), 256>>>(hh, W3, b3, nullptr, gmax, N, F2, F3);

    k_head<<<1, 256>>>(gmax, Wl1, bl1, Wl2, bl2, out);

    cudaEventDestroy(evFork);
    cudaEventDestroy(evJoin);
}